// round 11
// baseline (speedup 1.0000x reference)
#include <cuda_runtime.h>
#include <cuda_bf16.h>
#include <cstdint>
#include <cstddef>

#define QL 1024
#define BATCH 2
#define DM 1024
#define NH 16
#define DH 64
#define QB 2048            // Q*B rows
#define H3 3072            // 3*NH*DH
#define JR 2047            // 2*Q-1
#define JRP 2048           // padded
#define SCALEF 0.125f      // 1/sqrt(64)
#define EPSF 1e-5f

// -------- scratch (device globals; no allocations allowed) --------
__device__ float g_H[(size_t)QB * H3];            // qkv heads     25 MB
__device__ float g_RFB[(size_t)QL * 2 * DM];      // r @ [W_r_fw|W_r_bw] 8 MB
__device__ float g_AC[(size_t)32 * QL * QL];      // AC scores    134 MB
__device__ float g_BD[(size_t)32 * QL * JRP];     // BD raw       268 MB
__device__ float g_AO[(size_t)QB * DM];           // attn_out       8 MB

// bf16 hi/lo operands
__device__ __nv_bfloat16 g_Awh[(size_t)QB * DM], g_Awl[(size_t)QB * DM];
__device__ __nv_bfloat16 g_rh[(size_t)QL * DM], g_rl[(size_t)QL * DM];
__device__ __nv_bfloat16 g_Vh[(size_t)QB * DM], g_Vl[(size_t)QB * DM];
__device__ __nv_bfloat16 g_Wqt_h[(size_t)H3 * DM], g_Wqt_l[(size_t)H3 * DM];
__device__ __nv_bfloat16 g_Wfbt_h[(size_t)2 * DM * DM], g_Wfbt_l[(size_t)2 * DM * DM];
__device__ __nv_bfloat16 g_Wot_h[(size_t)DM * DM], g_Wot_l[(size_t)DM * DM];

// attention-core bf16 operands (per-(b,n) K-major layouts)
__device__ __nv_bfloat16 g_Qach[(size_t)32 * QL * DH], g_Qacl[(size_t)32 * QL * DH];
__device__ __nv_bfloat16 g_Qbdh[(size_t)32 * QL * DH], g_Qbdl[(size_t)32 * QL * DH];
__device__ __nv_bfloat16 g_Kh[(size_t)32 * QL * DH],  g_Kl[(size_t)32 * QL * DH];
__device__ __nv_bfloat16 g_VTh[(size_t)32 * DH * QL], g_VTl[(size_t)32 * DH * QL];
__device__ __nv_bfloat16 g_RKh[(size_t)NH * JRP * DH], g_RKl[(size_t)NH * JRP * DH];
__device__ __nv_bfloat16 g_Ph[(size_t)32 * QL * QL], g_Pl[(size_t)32 * QL * QL];

// ======================= small PTX helpers (portable) ======================
__device__ __forceinline__ uint32_t smem_to_u32(const void* p) {
  uint32_t a;
  asm("{ .reg .u64 t; cvta.to.shared.u64 t, %1; cvt.u32.u64 %0, t; }"
      : "=r"(a) : "l"(p));
  return a;
}
__device__ __forceinline__ void ldsm4(uint32_t* r, uint32_t a) {
  asm volatile("ldmatrix.sync.aligned.m8n8.x4.shared.b16 {%0,%1,%2,%3}, [%4];"
               : "=r"(r[0]), "=r"(r[1]), "=r"(r[2]), "=r"(r[3]) : "r"(a));
}
__device__ __forceinline__ void mma_bf16(float* c, const uint32_t* a,
                                         const uint32_t* b) {
  asm volatile(
      "mma.sync.aligned.m16n8k16.row.col.f32.bf16.bf16.f32 "
      "{%0,%1,%2,%3},{%4,%5,%6,%7},{%8,%9},{%0,%1,%2,%3};"
      : "+f"(c[0]), "+f"(c[1]), "+f"(c[2]), "+f"(c[3])
      : "r"(a[0]), "r"(a[1]), "r"(a[2]), "r"(a[3]), "r"(b[0]), "r"(b[1]));
}
__device__ __forceinline__ void cpa16(uint32_t dst, const void* src) {
  asm volatile("cp.async.cg.shared.global [%0], [%1], 16;" ::"r"(dst), "l"(src));
}
__device__ __forceinline__ void cp_commit() {
  asm volatile("cp.async.commit_group;");
}
template <int N>
__device__ __forceinline__ void cp_wait() {
  asm volatile("cp.async.wait_group %0;" ::"n"(N));
}
__device__ __forceinline__ void split1(float v, __nv_bfloat16& h, __nv_bfloat16& l) {
  h = __float2bfloat16(v);
  l = __float2bfloat16(v - __bfloat162float(h));
}

#define STR 40  // smem row stride in bf16 (80B): conflict-free ldmatrix, 16B-aligned

// ======== unified 2-stage cp.async pipelined mma core (3-term hi/lo) =======
// A [128, K] bf16 hi/lo; B [BN, K] bf16 hi/lo (both K-major, pre-offset).
// acc[2*NT][4], NT = BN/16.  dsm layout per stage: [Ah | Al | Bh | Bl].
template <int BN>
__device__ __forceinline__ void mma_core_pipe(
    const __nv_bfloat16* __restrict__ Ah, const __nv_bfloat16* __restrict__ Al,
    const __nv_bfloat16* __restrict__ Bh, const __nv_bfloat16* __restrict__ Bl,
    int K, char* dsm, float (*acc)[4]) {
  constexpr int NT = BN / 16;
  constexpr int ATB = 128 * STR * 2;  // bytes per A tile
  constexpr int BTB = BN * STR * 2;
  constexpr int OFF_BH = 2 * ATB;
  constexpr int STAGE = 2 * ATB + 2 * BTB;
  const int tid = threadIdx.x, wid = tid >> 5, lane = tid & 31;
  const int wm = (wid & 3) * 32;
  const int wn = (wid >> 2) * (BN / 2);
  const uint32_t base = smem_to_u32(dsm);
  const int aRow = wm + (lane & 15), aCol = (lane >> 4) * 8;
  const int bRow = wn + (lane & 7) + ((lane >> 4) & 1) * 8;
  const int bCol = ((lane >> 3) & 1) * 8;
  const uint32_t aOH = base + (uint32_t)(aRow * STR + aCol) * 2;
  const uint32_t bOH = base + OFF_BH + (uint32_t)(bRow * STR + bCol) * 2;
  const int row2 = tid >> 2, q2 = (tid & 3) * 8;
  const uint32_t sdst = base + (uint32_t)(row2 * STR + q2) * 2;

  auto issue = [&](int ce, int s) {
    const uint32_t sb = sdst + (uint32_t)(s * STAGE);
#pragma unroll
    for (int t = 0; t < 2; ++t) {
      const uint32_t so = sb + (uint32_t)(t * 64 * STR * 2);
      const size_t g = (size_t)(row2 + t * 64) * K + ce + q2;
      cpa16(so, Ah + g);
      cpa16(so + ATB, Al + g);
    }
#pragma unroll
    for (int t = 0; t < BN / 64; ++t) {
      const uint32_t so = sb + (uint32_t)(t * 64 * STR * 2);
      const size_t g = (size_t)(row2 + t * 64) * K + ce + q2;
      cpa16(so + OFF_BH, Bh + g);
      cpa16(so + OFF_BH + BTB, Bl + g);
    }
    cp_commit();
  };

  const int nch = K >> 5;
  issue(0, 0);
  for (int c = 0; c < nch; ++c) {
    const int s = c & 1;
    if (c + 1 < nch) {
      issue((c + 1) << 5, s ^ 1);
      cp_wait<1>();
    } else {
      cp_wait<0>();
    }
    __syncthreads();
    const uint32_t sof = (uint32_t)(s * STAGE);
#pragma unroll
    for (int ks = 0; ks < 2; ++ks) {
      const uint32_t kso = (uint32_t)(ks * 16) * 2;
      uint32_t ahf[2][4], alf[2][4], bhf[NT][2], blf[NT][2];
#pragma unroll
      for (int mt = 0; mt < 2; ++mt) {
        const uint32_t mo = (uint32_t)(mt * 16 * STR) * 2;
        ldsm4(ahf[mt], aOH + sof + mo + kso);
        ldsm4(alf[mt], aOH + sof + ATB + mo + kso);
      }
#pragma unroll
      for (int np = 0; np < NT / 2; ++np) {
        const uint32_t no = (uint32_t)(np * 16 * STR) * 2;
        uint32_t r[4];
        ldsm4(r, bOH + sof + no + kso);
        bhf[2 * np][0] = r[0]; bhf[2 * np][1] = r[1];
        bhf[2 * np + 1][0] = r[2]; bhf[2 * np + 1][1] = r[3];
        ldsm4(r, bOH + sof + BTB + no + kso);
        blf[2 * np][0] = r[0]; blf[2 * np][1] = r[1];
        blf[2 * np + 1][0] = r[2]; blf[2 * np + 1][1] = r[3];
      }
#pragma unroll
      for (int mt = 0; mt < 2; ++mt)
#pragma unroll
        for (int nt = 0; nt < NT; ++nt) {
          mma_bf16(acc[mt * NT + nt], ahf[mt], bhf[nt]);
          mma_bf16(acc[mt * NT + nt], ahf[mt], blf[nt]);
          mma_bf16(acc[mt * NT + nt], alf[mt], bhf[nt]);
        }
    }
    __syncthreads();
  }
}

#define SMEM128 (2 * (2 * 128 * STR * 2 + 2 * 128 * STR * 2))  // 81920
#define SMEM64  (2 * (2 * 128 * STR * 2 + 2 * 64 * STR * 2))   // 61440

// ================= elementwise fp32 -> bf16 hi/lo split ====================
__global__ void __launch_bounds__(256) split_kernel(
    const float* __restrict__ X, __nv_bfloat16* __restrict__ Xh,
    __nv_bfloat16* __restrict__ Xl, int n4) {
  int i = blockIdx.x * 256 + threadIdx.x;
  if (i >= n4) return;
  float4 v = ((const float4*)X)[i];
  __nv_bfloat16 h0, h1, h2, h3, l0, l1, l2, l3;
  split1(v.x, h0, l0); split1(v.y, h1, l1);
  split1(v.z, h2, l2); split1(v.w, h3, l3);
  ((__nv_bfloat162*)Xh)[2 * i]     = __halves2bfloat162(h0, h1);
  ((__nv_bfloat162*)Xh)[2 * i + 1] = __halves2bfloat162(h2, h3);
  ((__nv_bfloat162*)Xl)[2 * i]     = __halves2bfloat162(l0, l1);
  ((__nv_bfloat162*)Xl)[2 * i + 1] = __halves2bfloat162(l2, l3);
}

// ============== transpose + split: W[K,N] fp32 -> Wt[N,K] bf16 hi/lo =======
__global__ void __launch_bounds__(256) tsplit_kernel(
    const float* __restrict__ W, __nv_bfloat16* __restrict__ Oht,
    __nv_bfloat16* __restrict__ Olt, int K, int N) {
  __shared__ float t[32][33];
  const int n0 = blockIdx.x * 32, k0 = blockIdx.y * 32;
  const int tx = threadIdx.x, ty = threadIdx.y;
  for (int r = ty; r < 32; r += 8)
    t[r][tx] = W[(size_t)(k0 + r) * N + n0 + tx];
  __syncthreads();
  for (int r = ty; r < 32; r += 8) {
    float v = t[tx][r];  // = W[k0+tx][n0+r]
    __nv_bfloat16 h, l;
    split1(v, h, l);
    size_t o = (size_t)(n0 + r) * K + k0 + tx;
    Oht[o] = h;
    Olt[o] = l;
  }
}

// ============ weight-space NT GEMM (pipelined core) ========================
__global__ void __launch_bounds__(256) mma_gemm_nt(
    const __nv_bfloat16* __restrict__ Ah, const __nv_bfloat16* __restrict__ Al,
    const __nv_bfloat16* __restrict__ Bh, const __nv_bfloat16* __restrict__ Bl,
    float* __restrict__ C, int M, int N, int K) {
  extern __shared__ char dsm[];
  const int m0 = blockIdx.y * 128, n0 = blockIdx.x * 128;
  float acc[16][4] = {};
  mma_core_pipe<128>(Ah + (size_t)m0 * K, Al + (size_t)m0 * K,
                     Bh + (size_t)n0 * K, Bl + (size_t)n0 * K, K, dsm, acc);
  const int wid = threadIdx.x >> 5, lane = threadIdx.x & 31;
  const int wm = (wid & 3) * 32, wn = (wid >> 2) * 64;
  const int cr = lane >> 2, cc = (lane & 3) * 2;
#pragma unroll
  for (int mt = 0; mt < 2; ++mt) {
    const int r = m0 + wm + mt * 16 + cr;
#pragma unroll
    for (int nt = 0; nt < 8; ++nt) {
      const int col = n0 + wn + nt * 8 + cc;
      *(float2*)&C[(size_t)r * N + col] = make_float2(acc[mt * 8 + nt][0], acc[mt * 8 + nt][1]);
      *(float2*)&C[(size_t)(r + 8) * N + col] = make_float2(acc[mt * 8 + nt][2], acc[mt * 8 + nt][3]);
    }
  }
}

// ===== prep_heads: H -> Qac/Qbd/K (per-bn K-major) + VT (transposed) =======
__global__ void __launch_bounds__(256) prep_heads(
    const float* __restrict__ H, const float* __restrict__ rwb,
    const float* __restrict__ rrb,
    __nv_bfloat16* __restrict__ Qach, __nv_bfloat16* __restrict__ Qacl,
    __nv_bfloat16* __restrict__ Qbdh, __nv_bfloat16* __restrict__ Qbdl,
    __nv_bfloat16* __restrict__ Kh, __nv_bfloat16* __restrict__ Kl,
    __nv_bfloat16* __restrict__ VTh, __nv_bfloat16* __restrict__ VTl) {
  const int bn = blockIdx.y, b = bn >> 4, n = bn & 15;
  const int i0 = blockIdx.x * 64;
  const int tid = threadIdx.x;
  __shared__ float vs[64][65];
#pragma unroll
  for (int t = 0; t < 16; ++t) {
    int idx = tid + t * 256;
    int ii = idx >> 6, d = idx & 63;
    int i = i0 + ii;
    size_t hb = (size_t)(i * 2 + b) * H3 + n * DH + d;
    float q = H[hb], k = H[hb + DM], v = H[hb + 2 * DM];
    size_t o = ((size_t)bn * QL + i) * DH + d;
    __nv_bfloat16 h, l;
    split1(q + rwb[n * DH + d], h, l); Qach[o] = h; Qacl[o] = l;
    split1(q + rrb[n * DH + d], h, l); Qbdh[o] = h; Qbdl[o] = l;
    split1(k, h, l); Kh[o] = h; Kl[o] = l;
    vs[ii][d] = v;
  }
  __syncthreads();
#pragma unroll
  for (int t = 0; t < 16; ++t) {
    int idx = tid + t * 256;
    int d = idx >> 6, ii = idx & 63;
    __nv_bfloat16 h, l;
    split1(vs[ii][d], h, l);
    size_t o = ((size_t)bn * DH + d) * QL + i0 + ii;
    VTh[o] = h; VTl[o] = l;
  }
}

// ===== prep_rk: RFB -> RK[n][2048pad][64] bf16 hi/lo =======================
__global__ void __launch_bounds__(256) prep_rk(
    const float* __restrict__ RFB,
    __nv_bfloat16* __restrict__ RKh, __nv_bfloat16* __restrict__ RKl) {
  const int n = blockIdx.y;
  const int j0 = blockIdx.x * 64;
  const int tid = threadIdx.x;
#pragma unroll
  for (int t = 0; t < 16; ++t) {
    int idx = tid + t * 256;
    int jj = idx >> 6, d = idx & 63;
    int jr = j0 + jj;
    float v = 0.f;
    if (jr < QL) v = RFB[(size_t)jr * (2 * DM) + n * DH + d];
    else if (jr < JR) v = RFB[(size_t)(2046 - jr) * (2 * DM) + DM + n * DH + d];
    __nv_bfloat16 h, l;
    split1(v, h, l);
    size_t o = ((size_t)n * JRP + jr) * DH + d;
    RKh[o] = h; RKl[o] = l;
  }
}

// ================= AC via mma: AC[bn][i][j], K=64 ==========================
__global__ void __launch_bounds__(256) ac_mma(
    const __nv_bfloat16* __restrict__ Qh, const __nv_bfloat16* __restrict__ Ql,
    const __nv_bfloat16* __restrict__ Kh, const __nv_bfloat16* __restrict__ Kl,
    float* __restrict__ AC) {
  extern __shared__ char dsm[];
  const int bn = blockIdx.z;
  const size_t ab = ((size_t)bn * QL + blockIdx.y * 128) * DH;
  const size_t bb = ((size_t)bn * QL + blockIdx.x * 128) * DH;
  float acc[16][4] = {};
  mma_core_pipe<128>(Qh + ab, Ql + ab, Kh + bb, Kl + bb, DH, dsm, acc);
  const int wid = threadIdx.x >> 5, lane = threadIdx.x & 31;
  const int wm = (wid & 3) * 32, wn = (wid >> 2) * 64;
  const int cr = lane >> 2, cc = (lane & 3) * 2;
  float* C = AC + (size_t)bn * QL * QL + (size_t)(blockIdx.y * 128) * QL + blockIdx.x * 128;
#pragma unroll
  for (int mt = 0; mt < 2; ++mt) {
    const int r = wm + mt * 16 + cr;
#pragma unroll
    for (int nt = 0; nt < 8; ++nt) {
      const int col = wn + nt * 8 + cc;
      *(float2*)&C[(size_t)r * QL + col] = make_float2(acc[mt * 8 + nt][0], acc[mt * 8 + nt][1]);
      *(float2*)&C[(size_t)(r + 8) * QL + col] = make_float2(acc[mt * 8 + nt][2], acc[mt * 8 + nt][3]);
    }
  }
}

// ========= BD via mma: BD[bn][i][jr] (band-limited tiles), K=64 ============
__global__ void __launch_bounds__(256) bd_mma(
    const __nv_bfloat16* __restrict__ Qh, const __nv_bfloat16* __restrict__ Ql,
    const __nv_bfloat16* __restrict__ RKh, const __nv_bfloat16* __restrict__ RKl,
    float* __restrict__ BD) {
  const int i0 = blockIdx.y * 128, n0 = blockIdx.x * 128;
  if (i0 + n0 < 769 || i0 + n0 > 2046) return;  // outside rel-shift band
  extern __shared__ char dsm[];
  const int bn = blockIdx.z, n = bn & 15;
  const size_t ab = ((size_t)bn * QL + i0) * DH;
  const size_t bb = ((size_t)n * JRP + n0) * DH;
  float acc[16][4] = {};
  mma_core_pipe<128>(Qh + ab, Ql + ab, RKh + bb, RKl + bb, DH, dsm, acc);
  const int wid = threadIdx.x >> 5, lane = threadIdx.x & 31;
  const int wm = (wid & 3) * 32, wn = (wid >> 2) * 64;
  const int cr = lane >> 2, cc = (lane & 3) * 2;
  float* C = BD + (size_t)bn * QL * JRP + (size_t)i0 * JRP + n0;
#pragma unroll
  for (int mt = 0; mt < 2; ++mt) {
    const int r = wm + mt * 16 + cr;
#pragma unroll
    for (int nt = 0; nt < 8; ++nt) {
      const int col = wn + nt * 8 + cc;
      *(float2*)&C[(size_t)r * JRP + col] = make_float2(acc[mt * 8 + nt][0], acc[mt * 8 + nt][1]);
      *(float2*)&C[(size_t)(r + 8) * JRP + col] = make_float2(acc[mt * 8 + nt][2], acc[mt * 8 + nt][3]);
    }
  }
}

// ========== softmax -> bf16 hi/lo P ========================================
__global__ void __launch_bounds__(256) softmax_kernel(
    const float* __restrict__ AC, const float* __restrict__ BD,
    const unsigned char* __restrict__ mask,
    __nv_bfloat16* __restrict__ Ph, __nv_bfloat16* __restrict__ Pl) {
  const int i = blockIdx.x, bn = blockIdx.y, b = bn >> 4;
  const float* ac = AC + ((size_t)bn * QL + i) * QL;
  const float* bd = BD + (size_t)bn * QL * JRP + (size_t)i * JRP + (QL - 1 - i);
  const size_t pb = ((size_t)bn * QL + i) * QL;
  const int tid = threadIdx.x;
  float s[4];
  float mx = -3.4e38f;
#pragma unroll
  for (int t = 0; t < 4; ++t) {
    int j = tid + t * 256;
    float v = (ac[j] + bd[j]) * SCALEF;
    if (mask[j * BATCH + b]) v = -1e30f;
    s[t] = v;
    mx = fmaxf(mx, v);
  }
  __shared__ float red[8];
  __shared__ float red2[8];
#pragma unroll
  for (int o = 16; o; o >>= 1) mx = fmaxf(mx, __shfl_xor_sync(0xffffffffu, mx, o));
  if ((tid & 31) == 0) red[tid >> 5] = mx;
  __syncthreads();
  float bm = red[0];
#pragma unroll
  for (int k = 1; k < 8; ++k) bm = fmaxf(bm, red[k]);
  float sum = 0.f;
#pragma unroll
  for (int t = 0; t < 4; ++t) {
    s[t] = __expf(s[t] - bm);
    sum += s[t];
  }
#pragma unroll
  for (int o = 16; o; o >>= 1) sum += __shfl_xor_sync(0xffffffffu, sum, o);
  if ((tid & 31) == 0) red2[tid >> 5] = sum;
  __syncthreads();
  float tot = 0.f;
#pragma unroll
  for (int k = 0; k < 8; ++k) tot += red2[k];
  float inv = 1.f / tot;
#pragma unroll
  for (int t = 0; t < 4; ++t) {
    float pv_ = s[t] * inv;
    __nv_bfloat16 h, l;
    split1(pv_, h, l);
    Ph[pb + tid + t * 256] = h;
    Pl[pb + tid + t * 256] = l;
  }
}

// ========== PV via mma: V[i,b,n*64+d] = sum_j P[i][j] VT[d][j], K=1024 =====
__global__ void __launch_bounds__(256) pv_mma(
    const __nv_bfloat16* __restrict__ Ph, const __nv_bfloat16* __restrict__ Pl,
    const __nv_bfloat16* __restrict__ VTh, const __nv_bfloat16* __restrict__ VTl,
    __nv_bfloat16* __restrict__ Vh, __nv_bfloat16* __restrict__ Vl) {
  extern __shared__ char dsm[];
  const int bn = blockIdx.y, b = bn >> 4, n = bn & 15;
  const size_t ab = ((size_t)bn * QL + blockIdx.x * 128) * QL;
  const size_t bb = (size_t)bn * DH * QL;
  float acc[8][4] = {};
  mma_core_pipe<64>(Ph + ab, Pl + ab, VTh + bb, VTl + bb, QL, dsm, acc);
  const int wid = threadIdx.x >> 5, lane = threadIdx.x & 31;
  const int wm = (wid & 3) * 32, wn = (wid >> 2) * 32;
  const int cr = lane >> 2, cc = (lane & 3) * 2;
#pragma unroll
  for (int mt = 0; mt < 2; ++mt) {
    const int i = blockIdx.x * 128 + wm + mt * 16 + cr;
#pragma unroll
    for (int nt = 0; nt < 4; ++nt) {
      const int col = wn + nt * 8 + cc;
#pragma unroll
      for (int hh = 0; hh < 2; ++hh) {
        const int ir = i + hh * 8;
        const size_t o = (size_t)(ir * 2 + b) * DM + n * DH + col;
        float v0 = acc[mt * 4 + nt][hh * 2 + 0];
        float v1 = acc[mt * 4 + nt][hh * 2 + 1];
        __nv_bfloat16 h0, l0, h1, l1;
        split1(v0, h0, l0);
        split1(v1, h1, l1);
        *(__nv_bfloat162*)&Vh[o] = __halves2bfloat162(h0, h1);
        *(__nv_bfloat162*)&Vl[o] = __halves2bfloat162(l0, l1);
      }
    }
  }
}

// ========== residual + LayerNorm ==========================================
__global__ void __launch_bounds__(256) ln_kernel(
    const float* __restrict__ w, const float* __restrict__ AO,
    const float* __restrict__ gamma, const float* __restrict__ beta,
    float* __restrict__ out) {
  const int row = blockIdx.x;
  const int tid = threadIdx.x;
  const float* x1 = w + (size_t)row * DM;
  const float* x2 = AO + (size_t)row * DM;
  float x[4];
  float s = 0.f, s2 = 0.f;
#pragma unroll
  for (int t = 0; t < 4; ++t) {
    int d = tid + t * 256;
    x[t] = x1[d] + x2[d];
    s += x[t];
    s2 += x[t] * x[t];
  }
  __shared__ float r1[8], r2[8];
#pragma unroll
  for (int o = 16; o; o >>= 1) {
    s += __shfl_xor_sync(0xffffffffu, s, o);
    s2 += __shfl_xor_sync(0xffffffffu, s2, o);
  }
  if ((tid & 31) == 0) { r1[tid >> 5] = s; r2[tid >> 5] = s2; }
  __syncthreads();
  s = 0.f; s2 = 0.f;
#pragma unroll
  for (int k = 0; k < 8; ++k) { s += r1[k]; s2 += r2[k]; }
  const float mu = s * (1.f / DM);
  const float var = s2 * (1.f / DM) - mu * mu;
  const float inv = rsqrtf(var + EPSF);
  float* o = out + (size_t)row * DM;
#pragma unroll
  for (int t = 0; t < 4; ++t) {
    int d = tid + t * 256;
    o[d] = (x[t] - mu) * inv * gamma[d] + beta[d];
  }
}

// ===========================================================================
extern "C" void kernel_launch(void* const* d_in, const int* in_sizes, int n_in,
                              void* d_out, int out_size) {
  const float* w    = (const float*)d_in[0];   // [1024,2,1024]
  const float* r    = (const float*)d_in[1];   // [1024,1024]
  const float* rwb  = (const float*)d_in[2];   // [16,64]
  const float* rrb  = (const float*)d_in[3];   // [16,64]
  const unsigned char* mask = (const unsigned char*)d_in[4];  // [1024,2] bool
  const float* Wqkv = (const float*)d_in[5];   // [1024,3072]
  const float* Wrf  = (const float*)d_in[6];   // [1024,1024]
  const float* Wrb  = (const float*)d_in[7];   // [1024,1024]
  const float* Wo   = (const float*)d_in[8];   // [1024,1024]
  const float* lng  = (const float*)d_in[9];   // [1024]
  const float* lnb  = (const float*)d_in[10];  // [1024]
  float* out = (float*)d_out;                  // [1024,2,1024]

  void* p;
#define SYM(var, sym) cudaGetSymbolAddress(&p, sym); auto* var = (decltype(&sym[0]))p
  SYM(H, g_H); SYM(RFB, g_RFB); SYM(AC, g_AC); SYM(BD, g_BD); SYM(AO, g_AO);
  SYM(Awh, g_Awh); SYM(Awl, g_Awl); SYM(rh, g_rh); SYM(rl, g_rl);
  SYM(Vh, g_Vh); SYM(Vl, g_Vl);
  SYM(Wqt_h, g_Wqt_h); SYM(Wqt_l, g_Wqt_l);
  SYM(Wfbt_h, g_Wfbt_h); SYM(Wfbt_l, g_Wfbt_l);
  SYM(Wot_h, g_Wot_h); SYM(Wot_l, g_Wot_l);
  SYM(Qach, g_Qach); SYM(Qacl, g_Qacl);
  SYM(Qbdh, g_Qbdh); SYM(Qbdl, g_Qbdl);
  SYM(Kh, g_Kh); SYM(Kl, g_Kl);
  SYM(VTh, g_VTh); SYM(VTl, g_VTl);
  SYM(RKh, g_RKh); SYM(RKl, g_RKl);
  SYM(Ph, g_Ph); SYM(Pl, g_Pl);
#undef SYM

  cudaFuncSetAttribute(mma_gemm_nt, cudaFuncAttributeMaxDynamicSharedMemorySize, SMEM128);
  cudaFuncSetAttribute(ac_mma, cudaFuncAttributeMaxDynamicSharedMemorySize, SMEM128);
  cudaFuncSetAttribute(bd_mma, cudaFuncAttributeMaxDynamicSharedMemorySize, SMEM128);
  cudaFuncSetAttribute(pv_mma, cudaFuncAttributeMaxDynamicSharedMemorySize, SMEM64);

  // ---- operand prep: split activations, transpose+split weights ----
  split_kernel<<<(QB * DM / 4 + 255) / 256, 256>>>(w, Awh, Awl, QB * DM / 4);
  split_kernel<<<(QL * DM / 4 + 255) / 256, 256>>>(r, rh, rl, QL * DM / 4);
  tsplit_kernel<<<dim3(H3 / 32, DM / 32), dim3(32, 8)>>>(Wqkv, Wqt_h, Wqt_l, DM, H3);
  tsplit_kernel<<<dim3(DM / 32, DM / 32), dim3(32, 8)>>>(Wrf, Wfbt_h, Wfbt_l, DM, DM);
  tsplit_kernel<<<dim3(DM / 32, DM / 32), dim3(32, 8)>>>(
      Wrb, Wfbt_h + (size_t)DM * DM, Wfbt_l + (size_t)DM * DM, DM, DM);
  tsplit_kernel<<<dim3(DM / 32, DM / 32), dim3(32, 8)>>>(Wo, Wot_h, Wot_l, DM, DM);

  // 1) qkv projection: H[2048,3072] = w2d @ W_qkv    (pipelined mma)
  mma_gemm_nt<<<dim3(H3 / 128, QB / 128), 256, SMEM128>>>(
      Awh, Awl, Wqt_h, Wqt_l, H, QB, H3, DM);
  // 2) head prep (bf16 hi/lo per-(b,n) layouts + transposed V)
  prep_heads<<<dim3(QL / 64, 32), 256>>>(H, rwb, rrb, Qach, Qacl, Qbdh, Qbdl,
                                         Kh, Kl, VTh, VTl);
  // 3) fused r projections (fw|bw in one N=2048 GEMM) + rk table
  mma_gemm_nt<<<dim3(2 * DM / 128, QL / 128), 256, SMEM128>>>(
      rh, rl, Wfbt_h, Wfbt_l, RFB, QL, 2 * DM, DM);
  prep_rk<<<dim3(JRP / 64, NH), 256>>>(RFB, RKh, RKl);
  // 4) AC scores (tensor core)
  ac_mma<<<dim3(QL / 128, QL / 128, 32), 256, SMEM128>>>(Qach, Qacl, Kh, Kl, AC);
  // 5) BD raw scores (tensor core, band-limited)
  bd_mma<<<dim3(JRP / 128, QL / 128, 32), 256, SMEM128>>>(Qbdh, Qbdl, RKh, RKl, BD);
  // 6) shift + mask + softmax -> bf16 hi/lo P
  softmax_kernel<<<dim3(QL, 32), 256>>>(AC, BD, mask, Ph, Pl);
  // 7) P @ V (tensor core) -> bf16 hi/lo V directly
  pv_mma<<<dim3(QL / 128, 32), 256, SMEM64>>>(Ph, Pl, VTh, VTl, Vh, Vl);
  // 8) output projection
  mma_gemm_nt<<<dim3(DM / 128, QB / 128), 256, SMEM128>>>(
      Vh, Vl, Wot_h, Wot_l, AO, QB, DM, DM);
  // 9) residual + layernorm
  ln_kernel<<<QB, 256>>>(w, AO, lng, lnb, out);
}

// round 14
// speedup vs baseline: 1.3772x; 1.3772x over previous
#include <cuda_runtime.h>
#include <cuda_bf16.h>
#include <cstdint>
#include <cstddef>

#define QL 1024
#define BATCH 2
#define DM 1024
#define NH 16
#define DH 64
#define QB 2048            // Q*B rows
#define H3 3072            // 3*NH*DH
#define JR 2047            // 2*Q-1
#define JRP 2048           // padded
#define SCALEF 0.125f      // 1/sqrt(64)
#define EPSF 1e-5f

// -------- scratch (device globals; no allocations allowed) --------
__device__ float g_H[(size_t)QB * H3];            // qkv heads     25 MB
__device__ float g_RFB[(size_t)QL * 2 * DM];      // r @ [W_r_fw|W_r_bw] 8 MB
__device__ float g_AC[(size_t)32 * QL * QL];      // AC scores    134 MB
__device__ float g_BD[(size_t)32 * QL * JRP];     // BD raw       268 MB
__device__ float g_AO[(size_t)QB * DM];           // attn_out       8 MB

// bf16 hi/lo operands
__device__ __nv_bfloat16 g_Awh[(size_t)QB * DM], g_Awl[(size_t)QB * DM];
__device__ __nv_bfloat16 g_rh[(size_t)QL * DM], g_rl[(size_t)QL * DM];
__device__ __nv_bfloat16 g_Vh[(size_t)QB * DM], g_Vl[(size_t)QB * DM];
__device__ __nv_bfloat16 g_Wqt_h[(size_t)H3 * DM], g_Wqt_l[(size_t)H3 * DM];
__device__ __nv_bfloat16 g_Wfbt_h[(size_t)2 * DM * DM], g_Wfbt_l[(size_t)2 * DM * DM];
__device__ __nv_bfloat16 g_Wot_h[(size_t)DM * DM], g_Wot_l[(size_t)DM * DM];

// attention-core bf16 operands (per-(b,n) K-major layouts)
__device__ __nv_bfloat16 g_Qach[(size_t)32 * QL * DH], g_Qacl[(size_t)32 * QL * DH];
__device__ __nv_bfloat16 g_Qbdh[(size_t)32 * QL * DH], g_Qbdl[(size_t)32 * QL * DH];
__device__ __nv_bfloat16 g_Kh[(size_t)32 * QL * DH],  g_Kl[(size_t)32 * QL * DH];
__device__ __nv_bfloat16 g_VTh[(size_t)32 * DH * QL], g_VTl[(size_t)32 * DH * QL];
__device__ __nv_bfloat16 g_RKh[(size_t)NH * JRP * DH], g_RKl[(size_t)NH * JRP * DH];
__device__ __nv_bfloat16 g_Ph[(size_t)32 * QL * QL], g_Pl[(size_t)32 * QL * QL];

// ======================= small PTX helpers (portable) ======================
__device__ __forceinline__ uint32_t smem_to_u32(const void* p) {
  uint32_t a;
  asm("{ .reg .u64 t; cvta.to.shared.u64 t, %1; cvt.u32.u64 %0, t; }"
      : "=r"(a) : "l"(p));
  return a;
}
__device__ __forceinline__ void ldsm4(uint32_t* r, uint32_t a) {
  asm volatile("ldmatrix.sync.aligned.m8n8.x4.shared.b16 {%0,%1,%2,%3}, [%4];"
               : "=r"(r[0]), "=r"(r[1]), "=r"(r[2]), "=r"(r[3]) : "r"(a));
}
__device__ __forceinline__ void mma_bf16(float* c, const uint32_t* a,
                                         const uint32_t* b) {
  asm volatile(
      "mma.sync.aligned.m16n8k16.row.col.f32.bf16.bf16.f32 "
      "{%0,%1,%2,%3},{%4,%5,%6,%7},{%8,%9},{%0,%1,%2,%3};"
      : "+f"(c[0]), "+f"(c[1]), "+f"(c[2]), "+f"(c[3])
      : "r"(a[0]), "r"(a[1]), "r"(a[2]), "r"(a[3]), "r"(b[0]), "r"(b[1]));
}
__device__ __forceinline__ void split1(float v, __nv_bfloat16& h, __nv_bfloat16& l) {
  h = __float2bfloat16(v);
  l = __float2bfloat16(v - __bfloat162float(h));
}

#define STR 40  // smem row stride in bf16 (80B): conflict-free ldmatrix

// ====== round-10 static-smem mma core + optional register prefetch ========
// A [128, K] bf16 hi/lo; B [BN, K] bf16 hi/lo (both K-major, pre-offset).
// acc[2*NT][4], NT = BN/16.  PF: prefetch next chunk's global loads into
// registers before the current chunk's MMAs (K=1024 call sites only).
template <int BN, bool PF>
__device__ __forceinline__ void mma_core(
    const __nv_bfloat16* __restrict__ Ah, const __nv_bfloat16* __restrict__ Al,
    const __nv_bfloat16* __restrict__ Bh, const __nv_bfloat16* __restrict__ Bl,
    int K, __nv_bfloat16* sAh, __nv_bfloat16* sAl,
    __nv_bfloat16* sBh, __nv_bfloat16* sBl, float (*acc)[4]) {
  constexpr int NT = BN / 16;
  constexpr int BT = BN / 64;
  const int tid = threadIdx.x, wid = tid >> 5, lane = tid & 31;
  const int wm = (wid & 3) * 32;
  const int wn = (wid >> 2) * (BN / 2);
  const int aRow = wm + (lane & 15), aCol = (lane >> 4) * 8;
  const int bRow = wn + (lane & 7) + ((lane >> 4) & 1) * 8;
  const int bCol = ((lane >> 3) & 1) * 8;
  const uint32_t aOffH = smem_to_u32(sAh) + (uint32_t)(aRow * STR + aCol) * 2;
  const uint32_t aOffL = smem_to_u32(sAl) + (uint32_t)(aRow * STR + aCol) * 2;
  const uint32_t bOffH = smem_to_u32(sBh) + (uint32_t)(bRow * STR + bCol) * 2;
  const uint32_t bOffL = smem_to_u32(sBl) + (uint32_t)(bRow * STR + bCol) * 2;
  const int row2 = tid >> 2, q2 = (tid & 3) * 8;

  uint4 pa[2][2], pb[2][BT];
  auto gload = [&](int c) {
#pragma unroll
    for (int t = 0; t < 2; ++t) {
      const size_t g = (size_t)(row2 + t * 64) * K + c + q2;
      pa[0][t] = *(const uint4*)(Ah + g);
      pa[1][t] = *(const uint4*)(Al + g);
    }
#pragma unroll
    for (int t = 0; t < BT; ++t) {
      const size_t g = (size_t)(row2 + t * 64) * K + c + q2;
      pb[0][t] = *(const uint4*)(Bh + g);
      pb[1][t] = *(const uint4*)(Bl + g);
    }
  };
  if (PF) gload(0);

  for (int c = 0; c < K; c += 32) {
    __syncthreads();
    if (PF) {
#pragma unroll
      for (int t = 0; t < 2; ++t) {
        *(uint4*)&sAh[(row2 + t * 64) * STR + q2] = pa[0][t];
        *(uint4*)&sAl[(row2 + t * 64) * STR + q2] = pa[1][t];
      }
#pragma unroll
      for (int t = 0; t < BT; ++t) {
        *(uint4*)&sBh[(row2 + t * 64) * STR + q2] = pb[0][t];
        *(uint4*)&sBl[(row2 + t * 64) * STR + q2] = pb[1][t];
      }
      if (c + 32 < K) gload(c + 32);
    } else {
#pragma unroll
      for (int t = 0; t < 2; ++t) {
        const size_t g = (size_t)(row2 + t * 64) * K + c + q2;
        *(uint4*)&sAh[(row2 + t * 64) * STR + q2] = *(const uint4*)(Ah + g);
        *(uint4*)&sAl[(row2 + t * 64) * STR + q2] = *(const uint4*)(Al + g);
      }
#pragma unroll
      for (int t = 0; t < BT; ++t) {
        const size_t g = (size_t)(row2 + t * 64) * K + c + q2;
        *(uint4*)&sBh[(row2 + t * 64) * STR + q2] = *(const uint4*)(Bh + g);
        *(uint4*)&sBl[(row2 + t * 64) * STR + q2] = *(const uint4*)(Bl + g);
      }
    }
    __syncthreads();
#pragma unroll
    for (int ks = 0; ks < 2; ++ks) {
      const uint32_t kso = (uint32_t)(ks * 16) * 2;
      uint32_t ahf[2][4], alf[2][4], bhf[NT][2], blf[NT][2];
#pragma unroll
      for (int mt = 0; mt < 2; ++mt) {
        const uint32_t mo = (uint32_t)(mt * 16 * STR) * 2;
        ldsm4(ahf[mt], aOffH + mo + kso);
        ldsm4(alf[mt], aOffL + mo + kso);
      }
#pragma unroll
      for (int np = 0; np < NT / 2; ++np) {
        const uint32_t no = (uint32_t)(np * 16 * STR) * 2;
        uint32_t r[4];
        ldsm4(r, bOffH + no + kso);
        bhf[2 * np][0] = r[0]; bhf[2 * np][1] = r[1];
        bhf[2 * np + 1][0] = r[2]; bhf[2 * np + 1][1] = r[3];
        ldsm4(r, bOffL + no + kso);
        blf[2 * np][0] = r[0]; blf[2 * np][1] = r[1];
        blf[2 * np + 1][0] = r[2]; blf[2 * np + 1][1] = r[3];
      }
#pragma unroll
      for (int mt = 0; mt < 2; ++mt)
#pragma unroll
        for (int nt = 0; nt < NT; ++nt) {
          mma_bf16(acc[mt * NT + nt], ahf[mt], bhf[nt]);
          mma_bf16(acc[mt * NT + nt], ahf[mt], blf[nt]);
          mma_bf16(acc[mt * NT + nt], alf[mt], bhf[nt]);
        }
    }
  }
}

// ================= elementwise fp32 -> bf16 hi/lo split ====================
__global__ void __launch_bounds__(256) split_kernel(
    const float* __restrict__ X, __nv_bfloat16* __restrict__ Xh,
    __nv_bfloat16* __restrict__ Xl, int n4) {
  int i = blockIdx.x * 256 + threadIdx.x;
  if (i >= n4) return;
  float4 v = ((const float4*)X)[i];
  __nv_bfloat16 h0, h1, h2, h3, l0, l1, l2, l3;
  split1(v.x, h0, l0); split1(v.y, h1, l1);
  split1(v.z, h2, l2); split1(v.w, h3, l3);
  ((__nv_bfloat162*)Xh)[2 * i]     = __halves2bfloat162(h0, h1);
  ((__nv_bfloat162*)Xh)[2 * i + 1] = __halves2bfloat162(h2, h3);
  ((__nv_bfloat162*)Xl)[2 * i]     = __halves2bfloat162(l0, l1);
  ((__nv_bfloat162*)Xl)[2 * i + 1] = __halves2bfloat162(l2, l3);
}

// ============== transpose + split: W[K,N] fp32 -> Wt[N,K] bf16 hi/lo =======
__global__ void __launch_bounds__(256) tsplit_kernel(
    const float* __restrict__ W, __nv_bfloat16* __restrict__ Oht,
    __nv_bfloat16* __restrict__ Olt, int K, int N) {
  __shared__ float t[32][33];
  const int n0 = blockIdx.x * 32, k0 = blockIdx.y * 32;
  const int tx = threadIdx.x, ty = threadIdx.y;
  for (int r = ty; r < 32; r += 8)
    t[r][tx] = W[(size_t)(k0 + r) * N + n0 + tx];
  __syncthreads();
  for (int r = ty; r < 32; r += 8) {
    float v = t[tx][r];  // = W[k0+tx][n0+r]
    __nv_bfloat16 h, l;
    split1(v, h, l);
    size_t o = (size_t)(n0 + r) * K + k0 + tx;
    Oht[o] = h;
    Olt[o] = l;
  }
}

// ============ weight-space NT GEMM (prefetching core) ======================
__global__ void __launch_bounds__(256) mma_gemm_nt(
    const __nv_bfloat16* __restrict__ Ah, const __nv_bfloat16* __restrict__ Al,
    const __nv_bfloat16* __restrict__ Bh, const __nv_bfloat16* __restrict__ Bl,
    float* __restrict__ C, int M, int N, int K) {
  __shared__ __nv_bfloat16 sAh[128 * STR], sAl[128 * STR];
  __shared__ __nv_bfloat16 sBh[128 * STR], sBl[128 * STR];
  const int m0 = blockIdx.y * 128, n0 = blockIdx.x * 128;
  float acc[16][4] = {};
  mma_core<128, true>(Ah + (size_t)m0 * K, Al + (size_t)m0 * K,
                      Bh + (size_t)n0 * K, Bl + (size_t)n0 * K, K,
                      sAh, sAl, sBh, sBl, acc);
  const int wid = threadIdx.x >> 5, lane = threadIdx.x & 31;
  const int wm = (wid & 3) * 32, wn = (wid >> 2) * 64;
  const int cr = lane >> 2, cc = (lane & 3) * 2;
#pragma unroll
  for (int mt = 0; mt < 2; ++mt) {
    const int r = m0 + wm + mt * 16 + cr;
#pragma unroll
    for (int nt = 0; nt < 8; ++nt) {
      const int col = n0 + wn + nt * 8 + cc;
      *(float2*)&C[(size_t)r * N + col] = make_float2(acc[mt * 8 + nt][0], acc[mt * 8 + nt][1]);
      *(float2*)&C[(size_t)(r + 8) * N + col] = make_float2(acc[mt * 8 + nt][2], acc[mt * 8 + nt][3]);
    }
  }
}

// ===== prep_heads: H -> Qac/Qbd/K (per-bn K-major) + VT (transposed) =======
__global__ void __launch_bounds__(256) prep_heads(
    const float* __restrict__ H, const float* __restrict__ rwb,
    const float* __restrict__ rrb,
    __nv_bfloat16* __restrict__ Qach, __nv_bfloat16* __restrict__ Qacl,
    __nv_bfloat16* __restrict__ Qbdh, __nv_bfloat16* __restrict__ Qbdl,
    __nv_bfloat16* __restrict__ Kh, __nv_bfloat16* __restrict__ Kl,
    __nv_bfloat16* __restrict__ VTh, __nv_bfloat16* __restrict__ VTl) {
  const int bn = blockIdx.y, b = bn >> 4, n = bn & 15;
  const int i0 = blockIdx.x * 64;
  const int tid = threadIdx.x;
  __shared__ float vs[64][65];
#pragma unroll
  for (int t = 0; t < 16; ++t) {
    int idx = tid + t * 256;
    int ii = idx >> 6, d = idx & 63;
    int i = i0 + ii;
    size_t hb = (size_t)(i * 2 + b) * H3 + n * DH + d;
    float q = H[hb], k = H[hb + DM], v = H[hb + 2 * DM];
    size_t o = ((size_t)bn * QL + i) * DH + d;
    __nv_bfloat16 h, l;
    split1(q + rwb[n * DH + d], h, l); Qach[o] = h; Qacl[o] = l;
    split1(q + rrb[n * DH + d], h, l); Qbdh[o] = h; Qbdl[o] = l;
    split1(k, h, l); Kh[o] = h; Kl[o] = l;
    vs[ii][d] = v;
  }
  __syncthreads();
#pragma unroll
  for (int t = 0; t < 16; ++t) {
    int idx = tid + t * 256;
    int d = idx >> 6, ii = idx & 63;
    __nv_bfloat16 h, l;
    split1(vs[ii][d], h, l);
    size_t o = ((size_t)bn * DH + d) * QL + i0 + ii;
    VTh[o] = h; VTl[o] = l;
  }
}

// ===== prep_rk: RFB -> RK[n][2048pad][64] bf16 hi/lo =======================
__global__ void __launch_bounds__(256) prep_rk(
    const float* __restrict__ RFB,
    __nv_bfloat16* __restrict__ RKh, __nv_bfloat16* __restrict__ RKl) {
  const int n = blockIdx.y;
  const int j0 = blockIdx.x * 64;
  const int tid = threadIdx.x;
#pragma unroll
  for (int t = 0; t < 16; ++t) {
    int idx = tid + t * 256;
    int jj = idx >> 6, d = idx & 63;
    int jr = j0 + jj;
    float v = 0.f;
    if (jr < QL) v = RFB[(size_t)jr * (2 * DM) + n * DH + d];
    else if (jr < JR) v = RFB[(size_t)(2046 - jr) * (2 * DM) + DM + n * DH + d];
    __nv_bfloat16 h, l;
    split1(v, h, l);
    size_t o = ((size_t)n * JRP + jr) * DH + d;
    RKh[o] = h; RKl[o] = l;
  }
}

// ================= AC via mma: AC[bn][i][j], K=64 ==========================
__global__ void __launch_bounds__(256) ac_mma(
    const __nv_bfloat16* __restrict__ Qh, const __nv_bfloat16* __restrict__ Ql,
    const __nv_bfloat16* __restrict__ Kh, const __nv_bfloat16* __restrict__ Kl,
    float* __restrict__ AC) {
  __shared__ __nv_bfloat16 sAh[128 * STR], sAl[128 * STR];
  __shared__ __nv_bfloat16 sBh[128 * STR], sBl[128 * STR];
  const int bn = blockIdx.z;
  const size_t ab = ((size_t)bn * QL + blockIdx.y * 128) * DH;
  const size_t bb = ((size_t)bn * QL + blockIdx.x * 128) * DH;
  float acc[16][4] = {};
  mma_core<128, false>(Qh + ab, Ql + ab, Kh + bb, Kl + bb, DH,
                       sAh, sAl, sBh, sBl, acc);
  const int wid = threadIdx.x >> 5, lane = threadIdx.x & 31;
  const int wm = (wid & 3) * 32, wn = (wid >> 2) * 64;
  const int cr = lane >> 2, cc = (lane & 3) * 2;
  float* C = AC + (size_t)bn * QL * QL + (size_t)(blockIdx.y * 128) * QL + blockIdx.x * 128;
#pragma unroll
  for (int mt = 0; mt < 2; ++mt) {
    const int r = wm + mt * 16 + cr;
#pragma unroll
    for (int nt = 0; nt < 8; ++nt) {
      const int col = wn + nt * 8 + cc;
      *(float2*)&C[(size_t)r * QL + col] = make_float2(acc[mt * 8 + nt][0], acc[mt * 8 + nt][1]);
      *(float2*)&C[(size_t)(r + 8) * QL + col] = make_float2(acc[mt * 8 + nt][2], acc[mt * 8 + nt][3]);
    }
  }
}

// ========= BD via mma: BD[bn][i][jr] (band-limited tiles), K=64 ============
__global__ void __launch_bounds__(256) bd_mma(
    const __nv_bfloat16* __restrict__ Qh, const __nv_bfloat16* __restrict__ Ql,
    const __nv_bfloat16* __restrict__ RKh, const __nv_bfloat16* __restrict__ RKl,
    float* __restrict__ BD) {
  const int i0 = blockIdx.y * 128, n0 = blockIdx.x * 128;
  if (i0 + n0 < 769 || i0 + n0 > 2046) return;  // outside rel-shift band
  __shared__ __nv_bfloat16 sAh[128 * STR], sAl[128 * STR];
  __shared__ __nv_bfloat16 sBh[128 * STR], sBl[128 * STR];
  const int bn = blockIdx.z, n = bn & 15;
  const size_t ab = ((size_t)bn * QL + i0) * DH;
  const size_t bb = ((size_t)n * JRP + n0) * DH;
  float acc[16][4] = {};
  mma_core<128, false>(Qh + ab, Ql + ab, RKh + bb, RKl + bb, DH,
                       sAh, sAl, sBh, sBl, acc);
  const int wid = threadIdx.x >> 5, lane = threadIdx.x & 31;
  const int wm = (wid & 3) * 32, wn = (wid >> 2) * 64;
  const int cr = lane >> 2, cc = (lane & 3) * 2;
  float* C = BD + (size_t)bn * QL * JRP + (size_t)i0 * JRP + n0;
#pragma unroll
  for (int mt = 0; mt < 2; ++mt) {
    const int r = wm + mt * 16 + cr;
#pragma unroll
    for (int nt = 0; nt < 8; ++nt) {
      const int col = wn + nt * 8 + cc;
      *(float2*)&C[(size_t)r * JRP + col] = make_float2(acc[mt * 8 + nt][0], acc[mt * 8 + nt][1]);
      *(float2*)&C[(size_t)(r + 8) * JRP + col] = make_float2(acc[mt * 8 + nt][2], acc[mt * 8 + nt][3]);
    }
  }
}

// ========== softmax -> bf16 hi/lo P (vectorized, contiguous-4) =============
__global__ void __launch_bounds__(256) softmax_kernel(
    const float* __restrict__ AC, const float* __restrict__ BD,
    const unsigned char* __restrict__ mask,
    __nv_bfloat16* __restrict__ Ph, __nv_bfloat16* __restrict__ Pl) {
  const int i = blockIdx.x, bn = blockIdx.y, b = bn >> 4;
  const float* ac = AC + ((size_t)bn * QL + i) * QL;
  const float* bd = BD + (size_t)bn * QL * JRP + (size_t)i * JRP + (QL - 1 - i);
  const size_t pb = ((size_t)bn * QL + i) * QL;
  const int tid = threadIdx.x;
  const int j0 = tid * 4;
  float4 a4 = *(const float4*)(ac + j0);
  float s[4];
  s[0] = (a4.x + bd[j0 + 0]) * SCALEF;
  s[1] = (a4.y + bd[j0 + 1]) * SCALEF;
  s[2] = (a4.z + bd[j0 + 2]) * SCALEF;
  s[3] = (a4.w + bd[j0 + 3]) * SCALEF;
#pragma unroll
  for (int t = 0; t < 4; ++t)
    if (mask[(j0 + t) * BATCH + b]) s[t] = -1e30f;
  float mx = fmaxf(fmaxf(s[0], s[1]), fmaxf(s[2], s[3]));
  __shared__ float red[8];
  __shared__ float red2[8];
#pragma unroll
  for (int o = 16; o; o >>= 1) mx = fmaxf(mx, __shfl_xor_sync(0xffffffffu, mx, o));
  if ((tid & 31) == 0) red[tid >> 5] = mx;
  __syncthreads();
  float bm = red[0];
#pragma unroll
  for (int k = 1; k < 8; ++k) bm = fmaxf(bm, red[k]);
  float sum = 0.f;
#pragma unroll
  for (int t = 0; t < 4; ++t) {
    s[t] = __expf(s[t] - bm);
    sum += s[t];
  }
#pragma unroll
  for (int o = 16; o; o >>= 1) sum += __shfl_xor_sync(0xffffffffu, sum, o);
  if ((tid & 31) == 0) red2[tid >> 5] = sum;
  __syncthreads();
  float tot = 0.f;
#pragma unroll
  for (int k = 0; k < 8; ++k) tot += red2[k];
  float inv = 1.f / tot;
  __nv_bfloat16 h0, h1, h2, h3, l0, l1, l2, l3;
  split1(s[0] * inv, h0, l0);
  split1(s[1] * inv, h1, l1);
  split1(s[2] * inv, h2, l2);
  split1(s[3] * inv, h3, l3);
  *(__nv_bfloat162*)&Ph[pb + j0]     = __halves2bfloat162(h0, h1);
  *(__nv_bfloat162*)&Ph[pb + j0 + 2] = __halves2bfloat162(h2, h3);
  *(__nv_bfloat162*)&Pl[pb + j0]     = __halves2bfloat162(l0, l1);
  *(__nv_bfloat162*)&Pl[pb + j0 + 2] = __halves2bfloat162(l2, l3);
}

// ========== PV via mma: V[i,b,n*64+d] = sum_j P[i][j] VT[d][j], K=1024 =====
__global__ void __launch_bounds__(256) pv_mma(
    const __nv_bfloat16* __restrict__ Ph, const __nv_bfloat16* __restrict__ Pl,
    const __nv_bfloat16* __restrict__ VTh, const __nv_bfloat16* __restrict__ VTl,
    __nv_bfloat16* __restrict__ Vh, __nv_bfloat16* __restrict__ Vl) {
  __shared__ __nv_bfloat16 sAh[128 * STR], sAl[128 * STR];
  __shared__ __nv_bfloat16 sBh[64 * STR], sBl[64 * STR];
  const int bn = blockIdx.y, b = bn >> 4, n = bn & 15;
  const size_t ab = ((size_t)bn * QL + blockIdx.x * 128) * QL;
  const size_t bb = (size_t)bn * DH * QL;
  float acc[8][4] = {};
  mma_core<64, true>(Ph + ab, Pl + ab, VTh + bb, VTl + bb, QL,
                     sAh, sAl, sBh, sBl, acc);
  const int wid = threadIdx.x >> 5, lane = threadIdx.x & 31;
  const int wm = (wid & 3) * 32, wn = (wid >> 2) * 32;
  const int cr = lane >> 2, cc = (lane & 3) * 2;
#pragma unroll
  for (int mt = 0; mt < 2; ++mt) {
    const int i = blockIdx.x * 128 + wm + mt * 16 + cr;
#pragma unroll
    for (int nt = 0; nt < 4; ++nt) {
      const int col = wn + nt * 8 + cc;
#pragma unroll
      for (int hh = 0; hh < 2; ++hh) {
        const int ir = i + hh * 8;
        const size_t o = (size_t)(ir * 2 + b) * DM + n * DH + col;
        float v0 = acc[mt * 4 + nt][hh * 2 + 0];
        float v1 = acc[mt * 4 + nt][hh * 2 + 1];
        __nv_bfloat16 h0, l0, h1, l1;
        split1(v0, h0, l0);
        split1(v1, h1, l1);
        *(__nv_bfloat162*)&Vh[o] = __halves2bfloat162(h0, h1);
        *(__nv_bfloat162*)&Vl[o] = __halves2bfloat162(l0, l1);
      }
    }
  }
}

// ========== residual + LayerNorm ==========================================
__global__ void __launch_bounds__(256) ln_kernel(
    const float* __restrict__ w, const float* __restrict__ AO,
    const float* __restrict__ gamma, const float* __restrict__ beta,
    float* __restrict__ out) {
  const int row = blockIdx.x;
  const int tid = threadIdx.x;
  const float* x1 = w + (size_t)row * DM;
  const float* x2 = AO + (size_t)row * DM;
  float x[4];
  float s = 0.f, s2 = 0.f;
#pragma unroll
  for (int t = 0; t < 4; ++t) {
    int d = tid + t * 256;
    x[t] = x1[d] + x2[d];
    s += x[t];
    s2 += x[t] * x[t];
  }
  __shared__ float r1[8], r2[8];
#pragma unroll
  for (int o = 16; o; o >>= 1) {
    s += __shfl_xor_sync(0xffffffffu, s, o);
    s2 += __shfl_xor_sync(0xffffffffu, s2, o);
  }
  if ((tid & 31) == 0) { r1[tid >> 5] = s; r2[tid >> 5] = s2; }
  __syncthreads();
  s = 0.f; s2 = 0.f;
#pragma unroll
  for (int k = 0; k < 8; ++k) { s += r1[k]; s2 += r2[k]; }
  const float mu = s * (1.f / DM);
  const float var = s2 * (1.f / DM) - mu * mu;
  const float inv = rsqrtf(var + EPSF);
  float* o = out + (size_t)row * DM;
#pragma unroll
  for (int t = 0; t < 4; ++t) {
    int d = tid + t * 256;
    o[d] = (x[t] - mu) * inv * gamma[d] + beta[d];
  }
}

// ===========================================================================
extern "C" void kernel_launch(void* const* d_in, const int* in_sizes, int n_in,
                              void* d_out, int out_size) {
  const float* w    = (const float*)d_in[0];   // [1024,2,1024]
  const float* r    = (const float*)d_in[1];   // [1024,1024]
  const float* rwb  = (const float*)d_in[2];   // [16,64]
  const float* rrb  = (const float*)d_in[3];   // [16,64]
  const unsigned char* mask = (const unsigned char*)d_in[4];  // [1024,2] bool
  const float* Wqkv = (const float*)d_in[5];   // [1024,3072]
  const float* Wrf  = (const float*)d_in[6];   // [1024,1024]
  const float* Wrb  = (const float*)d_in[7];   // [1024,1024]
  const float* Wo   = (const float*)d_in[8];   // [1024,1024]
  const float* lng  = (const float*)d_in[9];   // [1024]
  const float* lnb  = (const float*)d_in[10];  // [1024]
  float* out = (float*)d_out;                  // [1024,2,1024]

  void* p;
#define SYM(var, sym) cudaGetSymbolAddress(&p, sym); auto* var = (decltype(&sym[0]))p
  SYM(H, g_H); SYM(RFB, g_RFB); SYM(AC, g_AC); SYM(BD, g_BD); SYM(AO, g_AO);
  SYM(Awh, g_Awh); SYM(Awl, g_Awl); SYM(rh, g_rh); SYM(rl, g_rl);
  SYM(Vh, g_Vh); SYM(Vl, g_Vl);
  SYM(Wqt_h, g_Wqt_h); SYM(Wqt_l, g_Wqt_l);
  SYM(Wfbt_h, g_Wfbt_h); SYM(Wfbt_l, g_Wfbt_l);
  SYM(Wot_h, g_Wot_h); SYM(Wot_l, g_Wot_l);
  SYM(Qach, g_Qach); SYM(Qacl, g_Qacl);
  SYM(Qbdh, g_Qbdh); SYM(Qbdl, g_Qbdl);
  SYM(Kh, g_Kh); SYM(Kl, g_Kl);
  SYM(VTh, g_VTh); SYM(VTl, g_VTl);
  SYM(RKh, g_RKh); SYM(RKl, g_RKl);
  SYM(Ph, g_Ph); SYM(Pl, g_Pl);
#undef SYM

  // ---- operand prep: split activations, transpose+split weights ----
  split_kernel<<<(QB * DM / 4 + 255) / 256, 256>>>(w, Awh, Awl, QB * DM / 4);
  split_kernel<<<(QL * DM / 4 + 255) / 256, 256>>>(r, rh, rl, QL * DM / 4);
  tsplit_kernel<<<dim3(H3 / 32, DM / 32), dim3(32, 8)>>>(Wqkv, Wqt_h, Wqt_l, DM, H3);
  tsplit_kernel<<<dim3(DM / 32, DM / 32), dim3(32, 8)>>>(Wrf, Wfbt_h, Wfbt_l, DM, DM);
  tsplit_kernel<<<dim3(DM / 32, DM / 32), dim3(32, 8)>>>(
      Wrb, Wfbt_h + (size_t)DM * DM, Wfbt_l + (size_t)DM * DM, DM, DM);
  tsplit_kernel<<<dim3(DM / 32, DM / 32), dim3(32, 8)>>>(Wo, Wot_h, Wot_l, DM, DM);

  // 1) qkv projection: H[2048,3072] = w2d @ W_qkv
  mma_gemm_nt<<<dim3(H3 / 128, QB / 128), 256>>>(Awh, Awl, Wqt_h, Wqt_l, H, QB, H3, DM);
  // 2) head prep (bf16 hi/lo per-(b,n) layouts + transposed V)
  prep_heads<<<dim3(QL / 64, 32), 256>>>(H, rwb, rrb, Qach, Qacl, Qbdh, Qbdl,
                                         Kh, Kl, VTh, VTl);
  // 3) fused r projections (fw|bw in one N=2048 GEMM) + rk table
  mma_gemm_nt<<<dim3(2 * DM / 128, QL / 128), 256>>>(
      rh, rl, Wfbt_h, Wfbt_l, RFB, QL, 2 * DM, DM);
  prep_rk<<<dim3(JRP / 64, NH), 256>>>(RFB, RKh, RKl);
  // 4) AC scores (tensor core)
  ac_mma<<<dim3(QL / 128, QL / 128, 32), 256>>>(Qach, Qacl, Kh, Kl, AC);
  // 5) BD raw scores (tensor core, band-limited)
  bd_mma<<<dim3(JRP / 128, QL / 128, 32), 256>>>(Qbdh, Qbdl, RKh, RKl, BD);
  // 6) shift + mask + softmax -> bf16 hi/lo P
  softmax_kernel<<<dim3(QL, 32), 256>>>(AC, BD, mask, Ph, Pl);
  // 7) P @ V (tensor core) -> bf16 hi/lo V directly
  pv_mma<<<dim3(QL / 128, 32), 256>>>(Ph, Pl, VTh, VTl, Vh, Vl);
  // 8) output projection
  mma_gemm_nt<<<dim3(DM / 128, QB / 128), 256>>>(Vh, Vl, Wot_h, Wot_l, AO, QB, DM, DM);
  // 9) residual + layernorm
  ln_kernel<<<QB, 256>>>(w, AO, lng, lnb, out);
}

// round 17
// speedup vs baseline: 1.4433x; 1.0480x over previous
#include <cuda_runtime.h>
#include <cuda_bf16.h>
#include <cstdint>
#include <cstddef>

#define QL 1024
#define BATCH 2
#define DM 1024
#define NH 16
#define DH 64
#define QB 2048            // Q*B rows
#define H3 3072            // 3*NH*DH
#define JR 2047            // 2*Q-1
#define JRP 2048           // padded
#define SCALEF 0.125f      // 1/sqrt(64)
#define EPSF 1e-5f

// -------- scratch (device globals; no allocations allowed) --------
__device__ float g_H[(size_t)QB * H3];            // qkv heads     25 MB
__device__ float g_RFB[(size_t)QL * 2 * DM];      // r @ [W_r_fw|W_r_bw] 8 MB
__device__ float g_AC[(size_t)32 * QL * QL];      // AC scores    134 MB
__device__ float g_BD[(size_t)32 * QL * JRP];     // BD raw       268 MB
__device__ float g_AO[(size_t)QB * DM];           // attn_out       8 MB

// bf16 hi/lo operands
__device__ __nv_bfloat16 g_Awh[(size_t)QB * DM], g_Awl[(size_t)QB * DM];
__device__ __nv_bfloat16 g_rh[(size_t)QL * DM], g_rl[(size_t)QL * DM];
__device__ __nv_bfloat16 g_Vh[(size_t)QB * DM], g_Vl[(size_t)QB * DM];
__device__ __nv_bfloat16 g_Wqt_h[(size_t)H3 * DM], g_Wqt_l[(size_t)H3 * DM];
__device__ __nv_bfloat16 g_Wfbt_h[(size_t)2 * DM * DM], g_Wfbt_l[(size_t)2 * DM * DM];
__device__ __nv_bfloat16 g_Wot_h[(size_t)DM * DM], g_Wot_l[(size_t)DM * DM];

// attention-core bf16 operands (per-(b,n) K-major layouts)
__device__ __nv_bfloat16 g_Qach[(size_t)32 * QL * DH], g_Qacl[(size_t)32 * QL * DH];
__device__ __nv_bfloat16 g_Qbdh[(size_t)32 * QL * DH], g_Qbdl[(size_t)32 * QL * DH];
__device__ __nv_bfloat16 g_Kh[(size_t)32 * QL * DH],  g_Kl[(size_t)32 * QL * DH];
__device__ __nv_bfloat16 g_VTh[(size_t)32 * DH * QL], g_VTl[(size_t)32 * DH * QL];
__device__ __nv_bfloat16 g_RKh[(size_t)NH * JRP * DH], g_RKl[(size_t)NH * JRP * DH];
__device__ __nv_bfloat16 g_Ph[(size_t)32 * QL * QL], g_Pl[(size_t)32 * QL * QL];

// ======================= small PTX helpers (portable) ======================
__device__ __forceinline__ uint32_t smem_to_u32(const void* p) {
  uint32_t a;
  asm("{ .reg .u64 t; cvta.to.shared.u64 t, %1; cvt.u32.u64 %0, t; }"
      : "=r"(a) : "l"(p));
  return a;
}
__device__ __forceinline__ void ldsm4(uint32_t* r, uint32_t a) {
  asm volatile("ldmatrix.sync.aligned.m8n8.x4.shared.b16 {%0,%1,%2,%3}, [%4];"
               : "=r"(r[0]), "=r"(r[1]), "=r"(r[2]), "=r"(r[3]) : "r"(a));
}
__device__ __forceinline__ void mma_bf16(float* c, const uint32_t* a,
                                         const uint32_t* b) {
  asm volatile(
      "mma.sync.aligned.m16n8k16.row.col.f32.bf16.bf16.f32 "
      "{%0,%1,%2,%3},{%4,%5,%6,%7},{%8,%9},{%0,%1,%2,%3};"
      : "+f"(c[0]), "+f"(c[1]), "+f"(c[2]), "+f"(c[3])
      : "r"(a[0]), "r"(a[1]), "r"(a[2]), "r"(a[3]), "r"(b[0]), "r"(b[1]));
}
__device__ __forceinline__ void split1(float v, __nv_bfloat16& h, __nv_bfloat16& l) {
  h = __float2bfloat16(v);
  l = __float2bfloat16(v - __bfloat162float(h));
}

#define STR 40  // smem row stride in bf16 (80B): conflict-free ldmatrix

// ====== static-smem mma core + optional register prefetch =================
template <int BN, bool PF>
__device__ __forceinline__ void mma_core(
    const __nv_bfloat16* __restrict__ Ah, const __nv_bfloat16* __restrict__ Al,
    const __nv_bfloat16* __restrict__ Bh, const __nv_bfloat16* __restrict__ Bl,
    int K, __nv_bfloat16* sAh, __nv_bfloat16* sAl,
    __nv_bfloat16* sBh, __nv_bfloat16* sBl, float (*acc)[4]) {
  constexpr int NT = BN / 16;
  constexpr int BT = BN / 64;
  const int tid = threadIdx.x, wid = tid >> 5, lane = tid & 31;
  const int wm = (wid & 3) * 32;
  const int wn = (wid >> 2) * (BN / 2);
  const int aRow = wm + (lane & 15), aCol = (lane >> 4) * 8;
  const int bRow = wn + (lane & 7) + ((lane >> 4) & 1) * 8;
  const int bCol = ((lane >> 3) & 1) * 8;
  const uint32_t aOffH = smem_to_u32(sAh) + (uint32_t)(aRow * STR + aCol) * 2;
  const uint32_t aOffL = smem_to_u32(sAl) + (uint32_t)(aRow * STR + aCol) * 2;
  const uint32_t bOffH = smem_to_u32(sBh) + (uint32_t)(bRow * STR + bCol) * 2;
  const uint32_t bOffL = smem_to_u32(sBl) + (uint32_t)(bRow * STR + bCol) * 2;
  const int row2 = tid >> 2, q2 = (tid & 3) * 8;

  uint4 pa[2][2], pb[2][BT];
  auto gload = [&](int c) {
#pragma unroll
    for (int t = 0; t < 2; ++t) {
      const size_t g = (size_t)(row2 + t * 64) * K + c + q2;
      pa[0][t] = *(const uint4*)(Ah + g);
      pa[1][t] = *(const uint4*)(Al + g);
    }
#pragma unroll
    for (int t = 0; t < BT; ++t) {
      const size_t g = (size_t)(row2 + t * 64) * K + c + q2;
      pb[0][t] = *(const uint4*)(Bh + g);
      pb[1][t] = *(const uint4*)(Bl + g);
    }
  };
  if (PF) gload(0);

  for (int c = 0; c < K; c += 32) {
    __syncthreads();
    if (PF) {
#pragma unroll
      for (int t = 0; t < 2; ++t) {
        *(uint4*)&sAh[(row2 + t * 64) * STR + q2] = pa[0][t];
        *(uint4*)&sAl[(row2 + t * 64) * STR + q2] = pa[1][t];
      }
#pragma unroll
      for (int t = 0; t < BT; ++t) {
        *(uint4*)&sBh[(row2 + t * 64) * STR + q2] = pb[0][t];
        *(uint4*)&sBl[(row2 + t * 64) * STR + q2] = pb[1][t];
      }
      if (c + 32 < K) gload(c + 32);
    } else {
#pragma unroll
      for (int t = 0; t < 2; ++t) {
        const size_t g = (size_t)(row2 + t * 64) * K + c + q2;
        *(uint4*)&sAh[(row2 + t * 64) * STR + q2] = *(const uint4*)(Ah + g);
        *(uint4*)&sAl[(row2 + t * 64) * STR + q2] = *(const uint4*)(Al + g);
      }
#pragma unroll
      for (int t = 0; t < BT; ++t) {
        const size_t g = (size_t)(row2 + t * 64) * K + c + q2;
        *(uint4*)&sBh[(row2 + t * 64) * STR + q2] = *(const uint4*)(Bh + g);
        *(uint4*)&sBl[(row2 + t * 64) * STR + q2] = *(const uint4*)(Bl + g);
      }
    }
    __syncthreads();
#pragma unroll
    for (int ks = 0; ks < 2; ++ks) {
      const uint32_t kso = (uint32_t)(ks * 16) * 2;
      uint32_t ahf[2][4], alf[2][4], bhf[NT][2], blf[NT][2];
#pragma unroll
      for (int mt = 0; mt < 2; ++mt) {
        const uint32_t mo = (uint32_t)(mt * 16 * STR) * 2;
        ldsm4(ahf[mt], aOffH + mo + kso);
        ldsm4(alf[mt], aOffL + mo + kso);
      }
#pragma unroll
      for (int np = 0; np < NT / 2; ++np) {
        const uint32_t no = (uint32_t)(np * 16 * STR) * 2;
        uint32_t r[4];
        ldsm4(r, bOffH + no + kso);
        bhf[2 * np][0] = r[0]; bhf[2 * np][1] = r[1];
        bhf[2 * np + 1][0] = r[2]; bhf[2 * np + 1][1] = r[3];
        ldsm4(r, bOffL + no + kso);
        blf[2 * np][0] = r[0]; blf[2 * np][1] = r[1];
        blf[2 * np + 1][0] = r[2]; blf[2 * np + 1][1] = r[3];
      }
#pragma unroll
      for (int mt = 0; mt < 2; ++mt)
#pragma unroll
        for (int nt = 0; nt < NT; ++nt) {
          mma_bf16(acc[mt * NT + nt], ahf[mt], bhf[nt]);
          mma_bf16(acc[mt * NT + nt], ahf[mt], blf[nt]);
          mma_bf16(acc[mt * NT + nt], alf[mt], bhf[nt]);
        }
    }
  }
}

// ====== shared 128x128 GEMM body: PF mma_core + fp32-strided epilogue ======
__device__ __forceinline__ void run_gemm_nt(
    const __nv_bfloat16* __restrict__ Ah, const __nv_bfloat16* __restrict__ Al,
    const __nv_bfloat16* __restrict__ Bh, const __nv_bfloat16* __restrict__ Bl,
    float* __restrict__ C, int N, int K, int m0, int n0, size_t ldc,
    __nv_bfloat16* sAh, __nv_bfloat16* sAl,
    __nv_bfloat16* sBh, __nv_bfloat16* sBl) {
  float acc[16][4] = {};
  mma_core<128, true>(Ah + (size_t)m0 * K, Al + (size_t)m0 * K,
                      Bh + (size_t)n0 * K, Bl + (size_t)n0 * K, K,
                      sAh, sAl, sBh, sBl, acc);
  const int wid = threadIdx.x >> 5, lane = threadIdx.x & 31;
  const int wm = (wid & 3) * 32, wn = (wid >> 2) * 64;
  const int cr = lane >> 2, cc = (lane & 3) * 2;
#pragma unroll
  for (int mt = 0; mt < 2; ++mt) {
    const int r = m0 + wm + mt * 16 + cr;
#pragma unroll
    for (int nt = 0; nt < 8; ++nt) {
      const int col = n0 + wn + nt * 8 + cc;
      *(float2*)&C[(size_t)r * ldc + col] = make_float2(acc[mt * 8 + nt][0], acc[mt * 8 + nt][1]);
      *(float2*)&C[(size_t)(r + 8) * ldc + col] = make_float2(acc[mt * 8 + nt][2], acc[mt * 8 + nt][3]);
    }
  }
}

// ========= merged elementwise fp32 -> bf16 hi/lo splits (w and r) ==========
__global__ void __launch_bounds__(256) split_all(
    const float* __restrict__ X0, __nv_bfloat16* __restrict__ X0h,
    __nv_bfloat16* __restrict__ X0l, int n40,
    const float* __restrict__ X1, __nv_bfloat16* __restrict__ X1h,
    __nv_bfloat16* __restrict__ X1l, int n41) {
  const float* X = blockIdx.z ? X1 : X0;
  __nv_bfloat16* Xh = blockIdx.z ? X1h : X0h;
  __nv_bfloat16* Xl = blockIdx.z ? X1l : X0l;
  const int n4 = blockIdx.z ? n41 : n40;
  int i = blockIdx.x * 256 + threadIdx.x;
  if (i >= n4) return;
  float4 v = ((const float4*)X)[i];
  __nv_bfloat16 h0, h1, h2, h3, l0, l1, l2, l3;
  split1(v.x, h0, l0); split1(v.y, h1, l1);
  split1(v.z, h2, l2); split1(v.w, h3, l3);
  ((__nv_bfloat162*)Xh)[2 * i]     = __halves2bfloat162(h0, h1);
  ((__nv_bfloat162*)Xh)[2 * i + 1] = __halves2bfloat162(h2, h3);
  ((__nv_bfloat162*)Xl)[2 * i]     = __halves2bfloat162(l0, l1);
  ((__nv_bfloat162*)Xl)[2 * i + 1] = __halves2bfloat162(l2, l3);
}

// ===== merged transpose+split for all four weights (z selects) =============
__global__ void __launch_bounds__(256) tsplit_all(
    const float* __restrict__ Wq, const float* __restrict__ Wf,
    const float* __restrict__ Wb, const float* __restrict__ Wo,
    __nv_bfloat16* __restrict__ Qh, __nv_bfloat16* __restrict__ Ql_,
    __nv_bfloat16* __restrict__ Fh, __nv_bfloat16* __restrict__ Fl,
    __nv_bfloat16* __restrict__ Oh, __nv_bfloat16* __restrict__ Ol) {
  const int z = blockIdx.z;
  const float* W; __nv_bfloat16 *Oht, *Olt; int N;
  if (z == 0) { W = Wq; Oht = Qh; Olt = Ql_; N = H3; }
  else if (z == 1) { W = Wf; Oht = Fh; Olt = Fl; N = DM; }
  else if (z == 2) { W = Wb; Oht = Fh + (size_t)DM * DM; Olt = Fl + (size_t)DM * DM; N = DM; }
  else { W = Wo; Oht = Oh; Olt = Ol; N = DM; }
  if (blockIdx.x * 32 >= N) return;
  __shared__ float t[32][33];
  const int n0 = blockIdx.x * 32, k0 = blockIdx.y * 32;
  const int tx = threadIdx.x, ty = threadIdx.y;
  for (int r = ty; r < 32; r += 8)
    t[r][tx] = W[(size_t)(k0 + r) * N + n0 + tx];
  __syncthreads();
  for (int r = ty; r < 32; r += 8) {
    float v = t[tx][r];
    __nv_bfloat16 h, l;
    split1(v, h, l);
    size_t o = (size_t)(n0 + r) * DM + k0 + tx;
    Oht[o] = h;
    Olt[o] = l;
  }
}

// ============ merged qkv + rfb weight GEMM launch ==========================
__global__ void __launch_bounds__(256) gemm_qkv_rfb(
    const __nv_bfloat16* __restrict__ Awh, const __nv_bfloat16* __restrict__ Awl,
    const __nv_bfloat16* __restrict__ Wqt_h, const __nv_bfloat16* __restrict__ Wqt_l,
    float* __restrict__ H,
    const __nv_bfloat16* __restrict__ rh, const __nv_bfloat16* __restrict__ rl,
    const __nv_bfloat16* __restrict__ Wfbt_h, const __nv_bfloat16* __restrict__ Wfbt_l,
    float* __restrict__ RFB) {
  __shared__ __nv_bfloat16 sAh[128 * STR], sAl[128 * STR];
  __shared__ __nv_bfloat16 sBh[128 * STR], sBl[128 * STR];
  if (blockIdx.z == 0) {
    run_gemm_nt(Awh, Awl, Wqt_h, Wqt_l, H, H3, DM,
                blockIdx.y * 128, blockIdx.x * 128, H3, sAh, sAl, sBh, sBl);
  } else {
    if (blockIdx.x >= 16 || blockIdx.y >= 8) return;
    run_gemm_nt(rh, rl, Wfbt_h, Wfbt_l, RFB, 2 * DM, DM,
                blockIdx.y * 128, blockIdx.x * 128, 2 * DM, sAh, sAl, sBh, sBl);
  }
}

// ============ Wo output projection =========================================
__global__ void __launch_bounds__(256) gemm_wo(
    const __nv_bfloat16* __restrict__ Ah, const __nv_bfloat16* __restrict__ Al,
    const __nv_bfloat16* __restrict__ Bh, const __nv_bfloat16* __restrict__ Bl,
    float* __restrict__ C) {
  __shared__ __nv_bfloat16 sAh[128 * STR], sAl[128 * STR];
  __shared__ __nv_bfloat16 sBh[128 * STR], sBl[128 * STR];
  run_gemm_nt(Ah, Al, Bh, Bl, C, DM, DM, blockIdx.y * 128, blockIdx.x * 128,
              DM, sAh, sAl, sBh, sBl);
}

// ===== merged prep: heads (z=0) + rk table (z=1) ===========================
__global__ void __launch_bounds__(256) prep_all(
    const float* __restrict__ H, const float* __restrict__ rwb,
    const float* __restrict__ rrb, const float* __restrict__ RFB,
    __nv_bfloat16* __restrict__ Qach, __nv_bfloat16* __restrict__ Qacl,
    __nv_bfloat16* __restrict__ Qbdh, __nv_bfloat16* __restrict__ Qbdl,
    __nv_bfloat16* __restrict__ Kh, __nv_bfloat16* __restrict__ Kl,
    __nv_bfloat16* __restrict__ VTh, __nv_bfloat16* __restrict__ VTl,
    __nv_bfloat16* __restrict__ RKh, __nv_bfloat16* __restrict__ RKl) {
  const int tid = threadIdx.x;
  if (blockIdx.z == 0) {
    if (blockIdx.x >= 16) return;
    const int bn = blockIdx.y, b = bn >> 4, n = bn & 15;
    const int i0 = blockIdx.x * 64;
    __shared__ float vs[64][65];
#pragma unroll
    for (int t = 0; t < 16; ++t) {
      int idx = tid + t * 256;
      int ii = idx >> 6, d = idx & 63;
      int i = i0 + ii;
      size_t hb = (size_t)(i * 2 + b) * H3 + n * DH + d;
      float q = H[hb], k = H[hb + DM], v = H[hb + 2 * DM];
      size_t o = ((size_t)bn * QL + i) * DH + d;
      __nv_bfloat16 h, l;
      split1(q + rwb[n * DH + d], h, l); Qach[o] = h; Qacl[o] = l;
      split1(q + rrb[n * DH + d], h, l); Qbdh[o] = h; Qbdl[o] = l;
      split1(k, h, l); Kh[o] = h; Kl[o] = l;
      vs[ii][d] = v;
    }
    __syncthreads();
#pragma unroll
    for (int t = 0; t < 16; ++t) {
      int idx = tid + t * 256;
      int d = idx >> 6, ii = idx & 63;
      __nv_bfloat16 h, l;
      split1(vs[ii][d], h, l);
      size_t o = ((size_t)bn * DH + d) * QL + i0 + ii;
      VTh[o] = h; VTl[o] = l;
    }
  } else {
    if (blockIdx.y >= 16) return;
    const int n = blockIdx.y;
    const int j0 = blockIdx.x * 64;
#pragma unroll
    for (int t = 0; t < 16; ++t) {
      int idx = tid + t * 256;
      int jj = idx >> 6, d = idx & 63;
      int jr = j0 + jj;
      float v = 0.f;
      if (jr < QL) v = RFB[(size_t)jr * (2 * DM) + n * DH + d];
      else if (jr < JR) v = RFB[(size_t)(2046 - jr) * (2 * DM) + DM + n * DH + d];
      __nv_bfloat16 h, l;
      split1(v, h, l);
      size_t o = ((size_t)n * JRP + jr) * DH + d;
      RKh[o] = h; RKl[o] = l;
    }
  }
}

// ========= merged AC (z<32) + BD (z>=32) score MMAs, both PF, K=64 =========
__global__ void __launch_bounds__(256) scores_mma(
    const __nv_bfloat16* __restrict__ Qach, const __nv_bfloat16* __restrict__ Qacl,
    const __nv_bfloat16* __restrict__ Kh, const __nv_bfloat16* __restrict__ Kl,
    const __nv_bfloat16* __restrict__ Qbdh, const __nv_bfloat16* __restrict__ Qbdl,
    const __nv_bfloat16* __restrict__ RKh, const __nv_bfloat16* __restrict__ RKl,
    float* __restrict__ AC, float* __restrict__ BD) {
  __shared__ __nv_bfloat16 sAh[128 * STR], sAl[128 * STR];
  __shared__ __nv_bfloat16 sBh[128 * STR], sBl[128 * STR];
  const int z = blockIdx.z;
  const int i0 = blockIdx.y * 128;
  float acc[16][4] = {};
  const int wid = threadIdx.x >> 5, lane = threadIdx.x & 31;
  const int wm = (wid & 3) * 32, wn = (wid >> 2) * 64;
  const int cr = lane >> 2, cc = (lane & 3) * 2;
  if (z < 32) {  // AC
    if (blockIdx.x >= 8) return;
    const int bn = z, j0 = blockIdx.x * 128;
    const size_t ab = ((size_t)bn * QL + i0) * DH;
    const size_t bb = ((size_t)bn * QL + j0) * DH;
    mma_core<128, true>(Qach + ab, Qacl + ab, Kh + bb, Kl + bb, DH,
                        sAh, sAl, sBh, sBl, acc);
    float* C = AC + (size_t)bn * QL * QL + (size_t)i0 * QL + j0;
#pragma unroll
    for (int mt = 0; mt < 2; ++mt) {
      const int r = wm + mt * 16 + cr;
#pragma unroll
      for (int nt = 0; nt < 8; ++nt) {
        const int col = wn + nt * 8 + cc;
        *(float2*)&C[(size_t)r * QL + col] = make_float2(acc[mt * 8 + nt][0], acc[mt * 8 + nt][1]);
        *(float2*)&C[(size_t)(r + 8) * QL + col] = make_float2(acc[mt * 8 + nt][2], acc[mt * 8 + nt][3]);
      }
    }
  } else {  // BD (band-limited)
    const int n0 = blockIdx.x * 128;
    if (i0 + n0 < 769 || i0 + n0 > 2046) return;
    const int bn = z - 32, n = bn & 15;
    const size_t ab = ((size_t)bn * QL + i0) * DH;
    const size_t bb = ((size_t)n * JRP + n0) * DH;
    mma_core<128, true>(Qbdh + ab, Qbdl + ab, RKh + bb, RKl + bb, DH,
                        sAh, sAl, sBh, sBl, acc);
    float* C = BD + (size_t)bn * QL * JRP + (size_t)i0 * JRP + n0;
#pragma unroll
    for (int mt = 0; mt < 2; ++mt) {
      const int r = wm + mt * 16 + cr;
#pragma unroll
      for (int nt = 0; nt < 8; ++nt) {
        const int col = wn + nt * 8 + cc;
        *(float2*)&C[(size_t)r * JRP + col] = make_float2(acc[mt * 8 + nt][0], acc[mt * 8 + nt][1]);
        *(float2*)&C[(size_t)(r + 8) * JRP + col] = make_float2(acc[mt * 8 + nt][2], acc[mt * 8 + nt][3]);
      }
    }
  }
}

// ========== softmax -> bf16 hi/lo P (vectorized, contiguous-4) =============
__global__ void __launch_bounds__(256) softmax_kernel(
    const float* __restrict__ AC, const float* __restrict__ BD,
    const unsigned char* __restrict__ mask,
    __nv_bfloat16* __restrict__ Ph, __nv_bfloat16* __restrict__ Pl) {
  const int i = blockIdx.x, bn = blockIdx.y, b = bn >> 4;
  const float* ac = AC + ((size_t)bn * QL + i) * QL;
  const float* bd = BD + (size_t)bn * QL * JRP + (size_t)i * JRP + (QL - 1 - i);
  const size_t pb = ((size_t)bn * QL + i) * QL;
  const int tid = threadIdx.x;
  const int j0 = tid * 4;
  float4 a4 = *(const float4*)(ac + j0);
  float s[4];
  s[0] = (a4.x + bd[j0 + 0]) * SCALEF;
  s[1] = (a4.y + bd[j0 + 1]) * SCALEF;
  s[2] = (a4.z + bd[j0 + 2]) * SCALEF;
  s[3] = (a4.w + bd[j0 + 3]) * SCALEF;
#pragma unroll
  for (int t = 0; t < 4; ++t)
    if (mask[(j0 + t) * BATCH + b]) s[t] = -1e30f;
  float mx = fmaxf(fmaxf(s[0], s[1]), fmaxf(s[2], s[3]));
  __shared__ float red[8];
  __shared__ float red2[8];
#pragma unroll
  for (int o = 16; o; o >>= 1) mx = fmaxf(mx, __shfl_xor_sync(0xffffffffu, mx, o));
  if ((tid & 31) == 0) red[tid >> 5] = mx;
  __syncthreads();
  float bm = red[0];
#pragma unroll
  for (int k = 1; k < 8; ++k) bm = fmaxf(bm, red[k]);
  float sum = 0.f;
#pragma unroll
  for (int t = 0; t < 4; ++t) {
    s[t] = __expf(s[t] - bm);
    sum += s[t];
  }
#pragma unroll
  for (int o = 16; o; o >>= 1) sum += __shfl_xor_sync(0xffffffffu, sum, o);
  if ((tid & 31) == 0) red2[tid >> 5] = sum;
  __syncthreads();
  float tot = 0.f;
#pragma unroll
  for (int k = 0; k < 8; ++k) tot += red2[k];
  float inv = 1.f / tot;
  __nv_bfloat16 h0, h1, h2, h3, l0, l1, l2, l3;
  split1(s[0] * inv, h0, l0);
  split1(s[1] * inv, h1, l1);
  split1(s[2] * inv, h2, l2);
  split1(s[3] * inv, h3, l3);
  *(__nv_bfloat162*)&Ph[pb + j0]     = __halves2bfloat162(h0, h1);
  *(__nv_bfloat162*)&Ph[pb + j0 + 2] = __halves2bfloat162(h2, h3);
  *(__nv_bfloat162*)&Pl[pb + j0]     = __halves2bfloat162(l0, l1);
  *(__nv_bfloat162*)&Pl[pb + j0 + 2] = __halves2bfloat162(l2, l3);
}

// ========== PV via mma: V[i,b,n*64+d] = sum_j P[i][j] VT[d][j], K=1024 =====
__global__ void __launch_bounds__(256) pv_mma(
    const __nv_bfloat16* __restrict__ Ph, const __nv_bfloat16* __restrict__ Pl,
    const __nv_bfloat16* __restrict__ VTh, const __nv_bfloat16* __restrict__ VTl,
    __nv_bfloat16* __restrict__ Vh, __nv_bfloat16* __restrict__ Vl) {
  __shared__ __nv_bfloat16 sAh[128 * STR], sAl[128 * STR];
  __shared__ __nv_bfloat16 sBh[64 * STR], sBl[64 * STR];
  const int bn = blockIdx.y, b = bn >> 4, n = bn & 15;
  const size_t ab = ((size_t)bn * QL + blockIdx.x * 128) * QL;
  const size_t bb = (size_t)bn * DH * QL;
  float acc[8][4] = {};
  mma_core<64, true>(Ph + ab, Pl + ab, VTh + bb, VTl + bb, QL,
                     sAh, sAl, sBh, sBl, acc);
  const int wid = threadIdx.x >> 5, lane = threadIdx.x & 31;
  const int wm = (wid & 3) * 32, wn = (wid >> 2) * 32;
  const int cr = lane >> 2, cc = (lane & 3) * 2;
#pragma unroll
  for (int mt = 0; mt < 2; ++mt) {
    const int i = blockIdx.x * 128 + wm + mt * 16 + cr;
#pragma unroll
    for (int nt = 0; nt < 4; ++nt) {
      const int col = wn + nt * 8 + cc;
#pragma unroll
      for (int hh = 0; hh < 2; ++hh) {
        const int ir = i + hh * 8;
        const size_t o = (size_t)(ir * 2 + b) * DM + n * DH + col;
        float v0 = acc[mt * 4 + nt][hh * 2 + 0];
        float v1 = acc[mt * 4 + nt][hh * 2 + 1];
        __nv_bfloat16 h0, l0, h1, l1;
        split1(v0, h0, l0);
        split1(v1, h1, l1);
        *(__nv_bfloat162*)&Vh[o] = __halves2bfloat162(h0, h1);
        *(__nv_bfloat162*)&Vl[o] = __halves2bfloat162(l0, l1);
      }
    }
  }
}

// ========== residual + LayerNorm ==========================================
__global__ void __launch_bounds__(256) ln_kernel(
    const float* __restrict__ w, const float* __restrict__ AO,
    const float* __restrict__ gamma, const float* __restrict__ beta,
    float* __restrict__ out) {
  const int row = blockIdx.x;
  const int tid = threadIdx.x;
  const float* x1 = w + (size_t)row * DM;
  const float* x2 = AO + (size_t)row * DM;
  float x[4];
  float s = 0.f, s2 = 0.f;
#pragma unroll
  for (int t = 0; t < 4; ++t) {
    int d = tid + t * 256;
    x[t] = x1[d] + x2[d];
    s += x[t];
    s2 += x[t] * x[t];
  }
  __shared__ float r1[8], r2[8];
#pragma unroll
  for (int o = 16; o; o >>= 1) {
    s += __shfl_xor_sync(0xffffffffu, s, o);
    s2 += __shfl_xor_sync(0xffffffffu, s2, o);
  }
  if ((tid & 31) == 0) { r1[tid >> 5] = s; r2[tid >> 5] = s2; }
  __syncthreads();
  s = 0.f; s2 = 0.f;
#pragma unroll
  for (int k = 0; k < 8; ++k) { s += r1[k]; s2 += r2[k]; }
  const float mu = s * (1.f / DM);
  const float var = s2 * (1.f / DM) - mu * mu;
  const float inv = rsqrtf(var + EPSF);
  float* o = out + (size_t)row * DM;
#pragma unroll
  for (int t = 0; t < 4; ++t) {
    int d = tid + t * 256;
    o[d] = (x[t] - mu) * inv * gamma[d] + beta[d];
  }
}

// ===========================================================================
extern "C" void kernel_launch(void* const* d_in, const int* in_sizes, int n_in,
                              void* d_out, int out_size) {
  const float* w    = (const float*)d_in[0];   // [1024,2,1024]
  const float* r    = (const float*)d_in[1];   // [1024,1024]
  const float* rwb  = (const float*)d_in[2];   // [16,64]
  const float* rrb  = (const float*)d_in[3];   // [16,64]
  const unsigned char* mask = (const unsigned char*)d_in[4];  // [1024,2] bool
  const float* Wqkv = (const float*)d_in[5];   // [1024,3072]
  const float* Wrf  = (const float*)d_in[6];   // [1024,1024]
  const float* Wrb  = (const float*)d_in[7];   // [1024,1024]
  const float* Wo   = (const float*)d_in[8];   // [1024,1024]
  const float* lng  = (const float*)d_in[9];   // [1024]
  const float* lnb  = (const float*)d_in[10];  // [1024]
  float* out = (float*)d_out;                  // [1024,2,1024]

  void* p;
#define SYM(var, sym) cudaGetSymbolAddress(&p, sym); auto* var = (decltype(&sym[0]))p
  SYM(H, g_H); SYM(RFB, g_RFB); SYM(AC, g_AC); SYM(BD, g_BD); SYM(AO, g_AO);
  SYM(Awh, g_Awh); SYM(Awl, g_Awl); SYM(rh, g_rh); SYM(rl, g_rl);
  SYM(Vh, g_Vh); SYM(Vl, g_Vl);
  SYM(Wqt_h, g_Wqt_h); SYM(Wqt_l, g_Wqt_l);
  SYM(Wfbt_h, g_Wfbt_h); SYM(Wfbt_l, g_Wfbt_l);
  SYM(Wot_h, g_Wot_h); SYM(Wot_l, g_Wot_l);
  SYM(Qach, g_Qach); SYM(Qacl, g_Qacl);
  SYM(Qbdh, g_Qbdh); SYM(Qbdl, g_Qbdl);
  SYM(Kh, g_Kh); SYM(Kl, g_Kl);
  SYM(VTh, g_VTh); SYM(VTl, g_VTl);
  SYM(RKh, g_RKh); SYM(RKl, g_RKl);
  SYM(Ph, g_Ph); SYM(Pl, g_Pl);
#undef SYM

  // 0) operand prep: merged activation splits + merged weight tsplits
  split_all<<<dim3(2048, 1, 2), 256>>>(w, Awh, Awl, QB * DM / 4,
                                       r, rh, rl, QL * DM / 4);
  tsplit_all<<<dim3(96, 32, 4), dim3(32, 8)>>>(Wqkv, Wrf, Wrb, Wo,
                                               Wqt_h, Wqt_l, Wfbt_h, Wfbt_l,
                                               Wot_h, Wot_l);
  // 1) merged qkv + fused r projections GEMM
  gemm_qkv_rfb<<<dim3(24, 16, 2), 256>>>(Awh, Awl, Wqt_h, Wqt_l, H,
                                         rh, rl, Wfbt_h, Wfbt_l, RFB);
  // 2) merged head prep + rk table
  prep_all<<<dim3(32, 32, 2), 256>>>(H, rwb, rrb, RFB,
                                     Qach, Qacl, Qbdh, Qbdl, Kh, Kl,
                                     VTh, VTl, RKh, RKl);
  // 3) merged AC + BD score MMAs (both register-prefetched)
  scores_mma<<<dim3(16, 8, 64), 256>>>(Qach, Qacl, Kh, Kl,
                                       Qbdh, Qbdl, RKh, RKl, AC, BD);
  // 4) shift + mask + softmax -> bf16 hi/lo P
  softmax_kernel<<<dim3(QL, 32), 256>>>(AC, BD, mask, Ph, Pl);
  // 5) P @ V (tensor core) -> bf16 hi/lo V directly
  pv_mma<<<dim3(QL / 128, 32), 256>>>(Ph, Pl, VTh, VTl, Vh, Vl);
  // 6) output projection
  gemm_wo<<<dim3(DM / 128, QB / 128), 256>>>(Vh, Vl, Wot_h, Wot_l, AO);
  // 7) residual + layernorm
  ln_kernel<<<QB, 256>>>(w, AO, lng, lnb, out);
}